// round 7
// baseline (speedup 1.0000x reference)
#include <cuda_runtime.h>
#include <cstdint>

// ---------------------------------------------------------------------------
// BMM_AB_I8_E_F32: C[b,m,n] = alpha * sum_k a[b,m,k]*b[b,k,n]
// B=16, M=1024, K=4096, N=4096.
//
// R2 finding: harness lowers via PTX .target sm_103 (no 'a') -> no tcgen05.
// Legacy tensor path: mma.sync.m16n8k32.s8 + ldmatrix + cp.async.
//
// R6 finding: rel_err was bit-identical (1.030818 = sqrt(17)/4) across three
// structurally different kernels => inputs are serialized as INT32 (the
// harness's dtype set has no int8; stub lists float32/int32/bf16 only).
// Reading int32 data as int8 predicts rel_err sqrt(1+1/16) — exact match.
//
// Fix: pre-pass converts int32 -> packed int8 into __device__ scratch, then
// the audited int8 IMMA GEMM runs unchanged on the scratch buffers.
// ---------------------------------------------------------------------------

#define BATCH   16
#define MDIM    1024
#define KDIM    4096
#define NDIM    4096

#define MT      128
#define NT      128
#define KT      64            // K bytes per pipeline chunk
#define KCHUNKS (KDIM / KT)   // 64
#define THREADS 256

#define A_STRIDE 80                    // bytes per m-row in SMEM
#define A_STAGE  (128 * A_STRIDE)      // 10240 B
#define B_STRIDE 528                   // bytes per k-word row (132 words)
#define B_WORDS  132
#define B_STAGE  (16 * B_STRIDE)       // 8448 B

#define A_ELEMS ((size_t)BATCH * MDIM * KDIM)   // 67108864
#define B_ELEMS ((size_t)BATCH * KDIM * NDIM)   // 268435456

// int8 scratch (static device arrays: allowed; no runtime allocation)
__device__ int8_t g_a8[A_ELEMS];
__device__ int8_t g_b8[B_ELEMS];

// ---------------------------------------------------------------------------
// int32 -> int8 pack: 16 ints (4x int4) -> 16 bytes (1x uint4) per iteration
// ---------------------------------------------------------------------------
__device__ __forceinline__ uint32_t pack4(int4 x) {
    uint32_t lo = __byte_perm((uint32_t)x.x, (uint32_t)x.y, 0x0040); // [x0b0, x1b0, -, -]
    uint32_t hi = __byte_perm((uint32_t)x.z, (uint32_t)x.w, 0x0040); // [x2b0, x3b0, -, -]
    return __byte_perm(lo, hi, 0x5410);                              // [x0,x1,x2,x3]
}

__global__ void __launch_bounds__(256)
conv_kernel(const int4* __restrict__ src, uint4* __restrict__ dst, long n16) {
    const long stride = (long)gridDim.x * blockDim.x;
    for (long i = (long)blockIdx.x * blockDim.x + threadIdx.x; i < n16; i += stride) {
        const int4 x0 = src[i * 4 + 0];
        const int4 x1 = src[i * 4 + 1];
        const int4 x2 = src[i * 4 + 2];
        const int4 x3 = src[i * 4 + 3];
        uint4 v;
        v.x = pack4(x0); v.y = pack4(x1); v.z = pack4(x2); v.w = pack4(x3);
        dst[i] = v;
    }
}

// ---------------------------------------------------------------------------
// IMMA GEMM (audited R6 structure, inputs = g_a8 / g_b8)
// ---------------------------------------------------------------------------
__device__ __forceinline__ uint32_t smem_u32(const void* p) {
    uint32_t a;
    asm("{ .reg .u64 t; cvta.to.shared.u64 t, %1; cvt.u32.u64 %0, t; }"
        : "=r"(a) : "l"(p));
    return a;
}

__device__ __forceinline__ void cpa16(uint32_t dst, const void* src) {
    asm volatile("cp.async.cg.shared.global [%0], [%1], 16;" :: "r"(dst), "l"(src));
}

__device__ __forceinline__ void ldmA(uint32_t a[4], uint32_t addr) {
    asm volatile("ldmatrix.sync.aligned.m8n8.x4.shared.b16 {%0,%1,%2,%3}, [%4];"
                 : "=r"(a[0]), "=r"(a[1]), "=r"(a[2]), "=r"(a[3]) : "r"(addr));
}

__device__ __forceinline__ void mma_s8(int c[4], const uint32_t a[4],
                                       uint32_t b0, uint32_t b1) {
    asm volatile(
        "mma.sync.aligned.m16n8k32.row.col.s32.s8.s8.s32 "
        "{%0,%1,%2,%3}, {%4,%5,%6,%7}, {%8,%9}, {%0,%1,%2,%3};"
        : "+r"(c[0]), "+r"(c[1]), "+r"(c[2]), "+r"(c[3])
        : "r"(a[0]), "r"(a[1]), "r"(a[2]), "r"(a[3]), "r"(b0), "r"(b1));
}

struct alignas(128) SmemT {
    int8_t a[2][A_STAGE];
    int8_t b[2][B_STAGE];
};

__global__ void __launch_bounds__(THREADS, 2)
bmm_i8_kernel(const float* __restrict__ alpha_p, float* __restrict__ out)
{
    __shared__ SmemT sm;

    const int tid  = threadIdx.x;
    const int wid  = tid >> 5;
    const int lane = tid & 31;

    // batch-major tile mapping: 256 tiles per batch (8 m x 32 n)
    const int bid   = blockIdx.x;
    const int batch = bid >> 8;
    const int rem   = bid & 255;
    const int m0    = (rem >> 5) * MT;
    const int n0    = (rem & 31) * NT;

    const int8_t* aB = g_a8 + (size_t)batch * MDIM * KDIM + (size_t)m0 * KDIM;
    const int8_t* bB = g_b8 + (size_t)batch * KDIM * NDIM + n0;
    float* outB = out + (size_t)batch * MDIM * NDIM;

    // warp layout: 2 (M) x 4 (N); warp tile 64m x 32n
    const int wm = wid >> 2;
    const int wn = wid & 3;

    const uint32_t sA[2] = { smem_u32(sm.a[0]), smem_u32(sm.a[1]) };
    uint32_t* const sBw[2] = { reinterpret_cast<uint32_t*>(sm.b[0]),
                               reinterpret_cast<uint32_t*>(sm.b[1]) };

    const int ar0 = tid >> 2;
    const int ac0 = (tid & 3) << 4;
    const int nb  = tid & 31;
    const int kb0 = tid >> 5;

    int cacc[4][4][4];
#pragma unroll
    for (int i = 0; i < 4; i++)
#pragma unroll
        for (int j = 0; j < 4; j++)
#pragma unroll
            for (int r = 0; r < 4; r++) cacc[i][j][r] = 0;

    auto loadA = [&](int chunk, int stg) {
        const uint32_t base = sA[stg];
        const int kk = chunk * KT;
        cpa16(base + ar0 * A_STRIDE + ac0,        aB + (size_t)ar0 * KDIM + kk + ac0);
        cpa16(base + (ar0 + 64) * A_STRIDE + ac0, aB + (size_t)(ar0 + 64) * KDIM + kk + ac0);
    };
    auto ldgB = [&](int chunk, uint32_t w[8]) {
        const int kk = chunk * KT;
#pragma unroll
        for (int t = 0; t < 2; t++) {
            const int kb = kb0 + t * 8;
#pragma unroll
            for (int r = 0; r < 4; r++)
                w[t * 4 + r] = *reinterpret_cast<const uint32_t*>(
                    bB + (size_t)(kk + kb * 4 + r) * NDIM + nb * 4);
        }
    };
    auto stsB = [&](const uint32_t w[8], int stg) {
        uint32_t* sb = sBw[stg];
#pragma unroll
        for (int t = 0; t < 2; t++) {
            const uint32_t a0 = w[t*4+0], a1 = w[t*4+1], a2 = w[t*4+2], a3 = w[t*4+3];
            uint32_t t0 = __byte_perm(a0, a1, 0x5140);
            uint32_t t1 = __byte_perm(a0, a1, 0x7362);
            uint32_t t2 = __byte_perm(a2, a3, 0x5140);
            uint32_t t3 = __byte_perm(a2, a3, 0x7362);
            uint4 v;
            v.x = __byte_perm(t0, t2, 0x5410);
            v.y = __byte_perm(t0, t2, 0x7632);
            v.z = __byte_perm(t1, t3, 0x5410);
            v.w = __byte_perm(t1, t3, 0x7632);
            const int kb = kb0 + t * 8;
            *reinterpret_cast<uint4*>(sb + kb * B_WORDS + nb * 4) = v;
        }
    };
    auto compute = [&](int stg) {
        const uint32_t baseA = sA[stg];
        const uint32_t* sb = sBw[stg];
        const int mrow = wm * 64 + (lane & 15);
        const int khl  = lane >> 4;
#pragma unroll
        for (int ks = 0; ks < 2; ks++) {
            uint32_t af[4][4];
#pragma unroll
            for (int mi = 0; mi < 4; mi++)
                ldmA(af[mi], baseA + (uint32_t)(mrow + mi * 16) * A_STRIDE
                                   + (uint32_t)(ks * 2 + khl) * 16);
            uint32_t bf[4][2];
#pragma unroll
            for (int ni = 0; ni < 4; ni++) {
                const int nl = wn * 32 + ni * 8 + (lane >> 2);
                const int kwb = ks * 8 + (lane & 3);
                bf[ni][0] = sb[(kwb)     * B_WORDS + nl];
                bf[ni][1] = sb[(kwb + 4) * B_WORDS + nl];
            }
#pragma unroll
            for (int ni = 0; ni < 4; ni++)
#pragma unroll
                for (int mi = 0; mi < 4; mi++)
                    mma_s8(cacc[mi][ni], af[mi], bf[ni][0], bf[ni][1]);
        }
    };

    // ---- prologue ----
    uint32_t bw[8];
    loadA(0, 0);
    asm volatile("cp.async.commit_group;" ::: "memory");
    ldgB(0, bw);
    stsB(bw, 0);
    asm volatile("cp.async.wait_group 0;" ::: "memory");
    __syncthreads();

    // ---- mainloop ----
    for (int i = 0; i < KCHUNKS; i++) {
        const int cur = i & 1;
        const int nxt = cur ^ 1;
        const bool more = (i + 1) < KCHUNKS;
        if (more) {
            loadA(i + 1, nxt);
            asm volatile("cp.async.commit_group;" ::: "memory");
            ldgB(i + 1, bw);
        }
        compute(cur);
        if (more) {
            stsB(bw, nxt);
            asm volatile("cp.async.wait_group 0;" ::: "memory");
        }
        __syncthreads();
    }

    // ---- epilogue: s32 -> f32 * alpha, float2 stores ----
    const float alpha = *alpha_p;
#pragma unroll
    for (int mi = 0; mi < 4; mi++) {
#pragma unroll
        for (int ni = 0; ni < 4; ni++) {
            const int row = m0 + wm * 64 + mi * 16 + (lane >> 2);
            const int col = n0 + wn * 32 + ni * 8 + 2 * (lane & 3);
            float2 v0, v1;
            v0.x = (float)cacc[mi][ni][0] * alpha;
            v0.y = (float)cacc[mi][ni][1] * alpha;
            v1.x = (float)cacc[mi][ni][2] * alpha;
            v1.y = (float)cacc[mi][ni][3] * alpha;
            *reinterpret_cast<float2*>(outB + (size_t)row * NDIM + col) = v0;
            *reinterpret_cast<float2*>(outB + (size_t)(row + 8) * NDIM + col) = v1;
        }
    }
}

extern "C" void kernel_launch(void* const* d_in, const int* in_sizes, int n_in,
                              void* d_out, int out_size) {
    // Inputs are serialized as int32 (a, b) and float32 (alpha).
    // Identify by element count; fall back to positional order (a, b, alpha).
    const int* a32 = (const int*)d_in[0];
    const int* b32 = (const int*)d_in[1];
    const float* alpha = (const float*)(n_in > 2 ? d_in[2] : d_in[1]);
    for (int i = 0; i < n_in; i++) {
        const long long sz = in_sizes[i];
        if (sz == (long long)A_ELEMS)      a32 = (const int*)d_in[i];
        else if (sz == (long long)B_ELEMS) b32 = (const int*)d_in[i];
        else if (sz == 1)                  alpha = (const float*)d_in[i];
    }
    float* out = (float*)d_out;

    int8_t* a8 = nullptr;
    int8_t* b8 = nullptr;
    cudaGetSymbolAddress((void**)&a8, g_a8);
    cudaGetSymbolAddress((void**)&b8, g_b8);

    // Pass 1: int32 -> int8 conversion (HBM-bound, ~1.6 GB total)
    conv_kernel<<<2048, 256>>>((const int4*)a32, (uint4*)a8, (long)(A_ELEMS / 16));
    conv_kernel<<<2048, 256>>>((const int4*)b32, (uint4*)b8, (long)(B_ELEMS / 16));

    // Pass 2: int8 IMMA GEMM
    const int grid = BATCH * (MDIM / MT) * (NDIM / NT);  // 4096
    bmm_i8_kernel<<<grid, THREADS>>>(alpha, out);
}